// round 6
// baseline (speedup 1.0000x reference)
#include <cuda_runtime.h>
#include <mma.h>
#include <cstdint>
#include <math.h>

using namespace nvcuda;

constexpr int B_ = 64;
constexpr int N_ = 1024;
constexpr int D_ = 512;
constexpr int K_ = 64;
constexpr int C_ = K_ + N_;                      // 1088
constexpr long OUT_ELEMS = (long)B_ * K_ * D_;
constexpr long DOTS_OFF  = OUT_ELEMS;

#define TEMP_INV (1.0f / 0.07f)

__device__ float g_shat[K_ * D_];
__device__ float g_S[K_ * K_];
__device__ float g_attn[(long)B_ * K_ * C_];

__device__ __forceinline__ float to_tf32(float x) {
    asm("cvt.rna.tf32.f32 %0, %1;" : "=f"(x) : "f"(x));
    return x;
}
__device__ __forceinline__ float4 to_tf32_4(float4 v) {
    return {to_tf32(v.x), to_tf32(v.y), to_tf32(v.z), to_tf32(v.w)};
}

// ---------------------------------------------------------------------------
// K1: normalize slot embeddings
// ---------------------------------------------------------------------------
__global__ void k_slot_norm(const float* __restrict__ slot) {
    int i = blockIdx.x, t = threadIdx.x;
    float v[4]; float ss = 0.f;
#pragma unroll
    for (int j = 0; j < 4; j++) { v[j] = slot[i * D_ + t + j * 128]; ss += v[j] * v[j]; }
#pragma unroll
    for (int o = 16; o; o >>= 1) ss += __shfl_xor_sync(0xffffffffu, ss, o);
    __shared__ float red[4];
    if ((t & 31) == 0) red[t >> 5] = ss;
    __syncthreads();
    float inv = 1.f / fmaxf(sqrtf(red[0] + red[1] + red[2] + red[3]), 1e-12f);
#pragma unroll
    for (int j = 0; j < 4; j++) g_shat[i * D_ + t + j * 128] = v[j] * inv;
}

// ---------------------------------------------------------------------------
// K2: S = Shat @ Shat^T (tiny, fp32 exact)
// ---------------------------------------------------------------------------
__global__ void k_slot_S() {
    int i = blockIdx.x, j = threadIdx.x;
    const float4* a = (const float4*)(g_shat + i * D_);
    const float4* b = (const float4*)(g_shat + j * D_);
    float acc = 0.f;
#pragma unroll 8
    for (int d = 0; d < D_ / 4; d++) {
        float4 x = a[d], y = b[d];
        acc += x.x * y.x + x.y * y.y + x.z * y.z + x.w * y.w;
    }
    g_S[i * K_ + j] = acc;
}

// nop: aligns ncu's captured (4th) launch onto k_dots
__global__ void k_nop() {}

// ---------------------------------------------------------------------------
// K3: dots key-part via wmma tf32. CTA: 128 keys x 64 slots, 4 warps,
// warp tile 32 keys x 64 slots (c[2][4]). K=512 in 16 chunks of 32.
// Conflict-free smem (ld 36). Fuses key row norms. Reg-prefetch pipeline.
// ---------------------------------------------------------------------------
constexpr int SD_KINV = 0;                        // 128
constexpr int SD_AS   = 128;                      // 2 x 128 x 36 = 9216 (unioned w/ CS)
constexpr int SD_CS   = SD_AS;                    // 64 x 132 = 8448 (after mainloop)
constexpr int SD_BS   = SD_AS + 2 * 128 * 36;     // 2 x 64 x 36 = 4608
constexpr int SD_TOT  = SD_BS + 2 * 64 * 36;      // 13952 floats = 55808 B

__global__ __launch_bounds__(128) void k_dots(const float* __restrict__ key,
                                              float* __restrict__ dout) {
    extern __shared__ float smf[];
    const int t = threadIdx.x, wid = t >> 5;
    const int b = blockIdx.y, n0blk = blockIdx.x * 128;
    const float* keyb = key + (long)b * N_ * D_;

    const int m0 = wid * 32;               // warp's key offset (N dim of output tile)

    wmma::fragment<wmma::accumulator, 16, 16, 8, float> c[2][4];
#pragma unroll
    for (int i = 0; i < 2; i++)
#pragma unroll
        for (int j = 0; j < 4; j++) wmma::fill_fragment(c[i][j], 0.f);

    const int rA = t >> 3, fA = t & 7;      // A staging: rows rA+16q, col fA
    float ss[8] = {0, 0, 0, 0, 0, 0, 0, 0};
    float4 pa[8], pb[4];

    auto ldg_chunk = [&](int jc) {
        const int d0 = jc * 32;
#pragma unroll
        for (int q = 0; q < 8; q++) {
            int r = rA + 16 * q;
            float4 v = *(const float4*)(keyb + (long)(n0blk + r) * D_ + d0 + fA * 4);
            ss[q] += v.x * v.x + v.y * v.y + v.z * v.z + v.w * v.w;
            pa[q] = v;
        }
#pragma unroll
        for (int q = 0; q < 4; q++) {
            int idx = t + 128 * q;
            int s = idx >> 3, f = idx & 7;
            pb[q] = *(const float4*)(g_shat + s * D_ + d0 + f * 4);
        }
    };
    auto sts_chunk = [&](int buf) {
        float* As = smf + SD_AS + buf * (128 * 36);
        float* Bs = smf + SD_BS + buf * (64 * 36);
#pragma unroll
        for (int q = 0; q < 8; q++)
            *(float4*)(As + (rA + 16 * q) * 36 + fA * 4) = to_tf32_4(pa[q]);
#pragma unroll
        for (int q = 0; q < 4; q++) {
            int idx = t + 128 * q;
            *(float4*)(Bs + (idx >> 3) * 36 + (idx & 7) * 4) = to_tf32_4(pb[q]);
        }
    };

    ldg_chunk(0);
    sts_chunk(0);
    __syncthreads();

    for (int jc = 0; jc < 16; jc++) {
        const int buf = jc & 1;
        const bool more = (jc + 1 < 16);
        if (more) ldg_chunk(jc + 1);
        float* As = smf + SD_AS + buf * (128 * 36);
        float* Bs = smf + SD_BS + buf * (64 * 36);
#pragma unroll
        for (int kk = 0; kk < 4; kk++) {
            int k0 = kk * 8;
            wmma::fragment<wmma::matrix_a, 16, 16, 8, wmma::precision::tf32, wmma::row_major> a0, a1;
            wmma::load_matrix_sync(a0, As + (m0)      * 36 + k0, 36);
            wmma::load_matrix_sync(a1, As + (m0 + 16) * 36 + k0, 36);
#pragma unroll
            for (int j = 0; j < 4; j++) {
                wmma::fragment<wmma::matrix_b, 16, 16, 8, wmma::precision::tf32, wmma::col_major> bf;
                wmma::load_matrix_sync(bf, Bs + (16 * j) * 36 + k0, 36);
                wmma::mma_sync(c[0][j], a0, bf, c[0][j]);
                wmma::mma_sync(c[1][j], a1, bf, c[1][j]);
            }
        }
        if (more) sts_chunk(buf ^ 1);
        __syncthreads();
    }

    // key inverse norms (8 threads share each row)
#pragma unroll
    for (int q = 0; q < 8; q++) {
#pragma unroll
        for (int o = 1; o < 8; o <<= 1) ss[q] += __shfl_xor_sync(0xffffffffu, ss[q], o);
    }
    if (fA == 0) {
#pragma unroll
        for (int q = 0; q < 8; q++)
            smf[SD_KINV + rA + 16 * q] = 1.f / fmaxf(sqrtf(ss[q]), 1e-12f);
    }

    // C fragments -> smem col-major Cs[slot][key] (ld 132), unioned with As
#pragma unroll
    for (int i = 0; i < 2; i++)
#pragma unroll
        for (int j = 0; j < 4; j++)
            wmma::store_matrix_sync(smf + SD_CS + (16 * j) * 132 + (m0 + 16 * i),
                                    c[i][j], 132, wmma::mem_col_major);
    __syncthreads();

    // write dots key-part: thread -> slot s = t>>1, key half kg = t&1
    {
        int s = t >> 1, kg = t & 1;
        const float* src = smf + SD_CS + s * 132 + kg * 64;
        const float* kv  = smf + SD_KINV + kg * 64;
        float* dst = dout + DOTS_OFF + (long)b * K_ * C_ + (long)s * C_ + K_ + n0blk + kg * 64;
#pragma unroll
        for (int g = 0; g < 16; g++) {
            float4 w = {src[g * 4 + 0] * kv[g * 4 + 0], src[g * 4 + 1] * kv[g * 4 + 1],
                        src[g * 4 + 2] * kv[g * 4 + 2], src[g * 4 + 3] * kv[g * 4 + 3]};
            *(float4*)(dst + g * 4) = w;
        }
    }
}

// ---------------------------------------------------------------------------
// K4: row softmax with block-causal mask -> g_attn; slot-slot dots -> output.
// ---------------------------------------------------------------------------
__global__ __launch_bounds__(256) void k_softmax(float* __restrict__ dout) {
    int row  = (blockIdx.x * blockDim.x + threadIdx.x) >> 5;
    int lane = threadIdx.x & 31;
    int b = row >> 6, i = row & 63;

    float* drow = dout + DOTS_OFF + (long)b * K_ * C_ + (long)i * C_;

    float sv[2], kvv[32];
    float m = -1e30f;
#pragma unroll
    for (int r = 0; r < 2; r++) {
        int c = lane + r * 32;
        float s = g_S[i * K_ + c];
        sv[r] = s;
        drow[c] = s;
        if (c < i) m = fmaxf(m, s);
    }
#pragma unroll
    for (int r = 0; r < 32; r++) {
        float v = drow[K_ + lane + r * 32];
        kvv[r] = v;
        m = fmaxf(m, v);
    }
#pragma unroll
    for (int o = 16; o; o >>= 1) m = fmaxf(m, __shfl_xor_sync(0xffffffffu, m, o));

    float sum = 0.f, es[2], ek[32];
#pragma unroll
    for (int r = 0; r < 2; r++) {
        int c = lane + r * 32;
        float x = (c < i) ? __expf((sv[r] - m) * TEMP_INV) : 0.f;
        es[r] = x; sum += x;
    }
#pragma unroll
    for (int r = 0; r < 32; r++) {
        float x = __expf((kvv[r] - m) * TEMP_INV);
        ek[r] = x; sum += x;
    }
#pragma unroll
    for (int o = 16; o; o >>= 1) sum += __shfl_xor_sync(0xffffffffu, sum, o);

    float inv = 1.f / (sum * (1.f + 1e-7f));
    float* at = g_attn + (long)row * C_;
#pragma unroll
    for (int r = 0; r < 2; r++) at[lane + r * 32] = es[r] * inv;
#pragma unroll
    for (int r = 0; r < 32; r++) at[K_ + lane + r * 32] = ek[r] * inv;
}

// ---------------------------------------------------------------------------
// K5: out = attn_n @ [slots; key_b] via wmma tf32. CTA: 64 slots x 128 d,
// 4 warps, warp tile 32 slots x 64 d (c[2][4]). 34 chunks of 32 over C=1088.
// ---------------------------------------------------------------------------
constexpr int SO_AS  = 0;                         // 2 x 64 x 36 = 4608
constexpr int SO_BS  = SO_AS + 2 * 64 * 36;       // 2 x 32 x 132 = 8448
constexpr int SO_TOT = SO_BS + 2 * 32 * 132;      // 13056 floats = 52224 B

__global__ __launch_bounds__(128) void k_out(const float* __restrict__ slot,
                                             const float* __restrict__ key,
                                             float* __restrict__ dout) {
    extern __shared__ float smf[];
    const int t = threadIdx.x, wid = t >> 5;
    const int b = blockIdx.y, d0 = blockIdx.x * 128;
    const float* keyb  = key + (long)b * N_ * D_;
    const float* attnb = g_attn + (long)b * K_ * C_;

    const int m0 = (wid & 1) * 32;    // slot offset
    const int n0 = (wid >> 1) * 64;   // d offset

    wmma::fragment<wmma::accumulator, 16, 16, 8, float> c[2][4];
#pragma unroll
    for (int i = 0; i < 2; i++)
#pragma unroll
        for (int j = 0; j < 4; j++) wmma::fill_fragment(c[i][j], 0.f);

    float4 pa[4], pb[8];

    auto ldg_chunk = [&](int jc) {
        const int c0 = jc * 32;
#pragma unroll
        for (int q = 0; q < 4; q++) {
            int idx = t + 128 * q;
            int r = idx >> 3, f = idx & 7;
            pa[q] = *(const float4*)(attnb + (long)r * C_ + c0 + f * 4);
        }
#pragma unroll
        for (int q = 0; q < 8; q++) {
            int idx = t + 128 * q;
            int r = idx >> 5, f = idx & 31;
            int cc = c0 + r;
            const float* src = (cc < K_) ? (slot + (long)cc * D_ + d0 + f * 4)
                                         : (keyb + (long)(cc - K_) * D_ + d0 + f * 4);
            pb[q] = *(const float4*)src;
        }
    };
    auto sts_chunk = [&](int buf) {
        float* As = smf + SO_AS + buf * (64 * 36);
        float* Bs = smf + SO_BS + buf * (32 * 132);
#pragma unroll
        for (int q = 0; q < 4; q++) {
            int idx = t + 128 * q;
            *(float4*)(As + (idx >> 3) * 36 + (idx & 7) * 4) = to_tf32_4(pa[q]);
        }
#pragma unroll
        for (int q = 0; q < 8; q++) {
            int idx = t + 128 * q;
            *(float4*)(Bs + (idx >> 5) * 132 + (idx & 31) * 4) = to_tf32_4(pb[q]);
        }
    };

    ldg_chunk(0);
    sts_chunk(0);
    __syncthreads();

    for (int jc = 0; jc < 34; jc++) {
        const int buf = jc & 1;
        const bool more = (jc + 1 < 34);
        if (more) ldg_chunk(jc + 1);
        float* As = smf + SO_AS + buf * (64 * 36);
        float* Bs = smf + SO_BS + buf * (32 * 132);
#pragma unroll
        for (int kk = 0; kk < 4; kk++) {
            int k0 = kk * 8;
            wmma::fragment<wmma::matrix_a, 16, 16, 8, wmma::precision::tf32, wmma::row_major> a0, a1;
            wmma::load_matrix_sync(a0, As + (m0)      * 36 + k0, 36);
            wmma::load_matrix_sync(a1, As + (m0 + 16) * 36 + k0, 36);
#pragma unroll
            for (int j = 0; j < 4; j++) {
                wmma::fragment<wmma::matrix_b, 16, 16, 8, wmma::precision::tf32, wmma::row_major> bf;
                wmma::load_matrix_sync(bf, Bs + k0 * 132 + n0 + 16 * j, 132);
                wmma::mma_sync(c[0][j], a0, bf, c[0][j]);
                wmma::mma_sync(c[1][j], a1, bf, c[1][j]);
            }
        }
        if (more) sts_chunk(buf ^ 1);
        __syncthreads();
    }

    // direct global store: out[b][slot][d]
#pragma unroll
    for (int i = 0; i < 2; i++)
#pragma unroll
        for (int j = 0; j < 4; j++) {
            float* gp = dout + (long)b * K_ * D_ + (long)(m0 + 16 * i) * D_ + d0 + n0 + 16 * j;
            wmma::store_matrix_sync(gp, c[i][j], D_, wmma::mem_row_major);
        }
}

// ---------------------------------------------------------------------------
extern "C" void kernel_launch(void* const* d_in, const int* in_sizes, int n_in,
                              void* d_out, int out_size) {
    const float* key  = (const float*)d_in[0];
    const float* slot = (const float*)d_in[1];
    float* out = (float*)d_out;

    cudaFuncSetAttribute(k_dots, cudaFuncAttributeMaxDynamicSharedMemorySize, SD_TOT * 4);
    cudaFuncSetAttribute(k_out,  cudaFuncAttributeMaxDynamicSharedMemorySize, SO_TOT * 4);

    k_slot_norm<<<K_, 128>>>(slot);
    k_slot_S<<<K_, K_>>>();
    k_nop<<<1, 32>>>();                     // aligns ncu capture (4th launch) on k_dots
    k_dots<<<dim3(N_ / 128, B_), 128, SD_TOT * 4>>>(key, out);
    k_softmax<<<(B_ * K_) / 8, 256>>>(out);
    k_out<<<dim3(D_ / 128, B_), 128, SO_TOT * 4>>>(slot, key, out);
}

// round 8
// speedup vs baseline: 1.1204x; 1.1204x over previous
#include <cuda_runtime.h>
#include <mma.h>
#include <cstdint>
#include <math.h>

using namespace nvcuda;

constexpr int B_ = 64;
constexpr int N_ = 1024;
constexpr int D_ = 512;
constexpr int K_ = 64;
constexpr int C_ = K_ + N_;                      // 1088
constexpr long OUT_ELEMS = (long)B_ * K_ * D_;
constexpr long DOTS_OFF  = OUT_ELEMS;

#define TEMP_INV (1.0f / 0.07f)

__device__ float g_shat[K_ * D_];                // tf32-rounded normalized slots
__device__ float g_sninv[K_];                    // exact slot inverse norms
__device__ float g_S[K_ * K_];                   // exact slot-slot cosines
__device__ float g_attn[(long)B_ * K_ * C_];     // tf32-rounded attn weights

__device__ __forceinline__ float to_tf32(float x) {
    asm("cvt.rna.tf32.f32 %0, %1;" : "=f"(x) : "f"(x));
    return x;
}
__device__ __forceinline__ uint32_t smem_u32(const void* p) {
    uint32_t a;
    asm("{ .reg .u64 t; cvta.to.shared.u64 t, %1; cvt.u32.u64 %0, t; }" : "=r"(a) : "l"(p));
    return a;
}
__device__ __forceinline__ void cp16(uint32_t dst, const void* src) {
    asm volatile("cp.async.cg.shared.global [%0], [%1], 16;" :: "r"(dst), "l"(src));
}
__device__ __forceinline__ void cp_commit() {
    asm volatile("cp.async.commit_group;" ::: "memory");
}

// ---------------------------------------------------------------------------
// K1: normalize slots -> g_shat (tf32-rounded) + g_sninv (exact)
// ---------------------------------------------------------------------------
__global__ void k_slot_norm(const float* __restrict__ slot) {
    int i = blockIdx.x, t = threadIdx.x;
    float v[4]; float ss = 0.f;
#pragma unroll
    for (int j = 0; j < 4; j++) { v[j] = slot[i * D_ + t + j * 128]; ss += v[j] * v[j]; }
#pragma unroll
    for (int o = 16; o; o >>= 1) ss += __shfl_xor_sync(0xffffffffu, ss, o);
    __shared__ float red[4];
    if ((t & 31) == 0) red[t >> 5] = ss;
    __syncthreads();
    float inv = 1.f / fmaxf(sqrtf(red[0] + red[1] + red[2] + red[3]), 1e-12f);
#pragma unroll
    for (int j = 0; j < 4; j++) g_shat[i * D_ + t + j * 128] = to_tf32(v[j] * inv);
    if (t == 0) g_sninv[i] = inv;
}

// ---------------------------------------------------------------------------
// K2: S = norm(slot) @ norm(slot)^T, exact fp32 from raw slot + sninv
// ---------------------------------------------------------------------------
__global__ void k_slot_S(const float* __restrict__ slot) {
    int i = blockIdx.x, j = threadIdx.x;
    const float4* a = (const float4*)(slot + i * D_);
    const float4* b = (const float4*)(slot + j * D_);
    float acc = 0.f;
#pragma unroll 8
    for (int d = 0; d < D_ / 4; d++) {
        float4 x = a[d], y = b[d];
        acc += x.x * y.x + x.y * y.y + x.z * y.z + x.w * y.w;
    }
    g_S[i * K_ + j] = acc * g_sninv[i] * g_sninv[j];
}

// nop: aligns ncu's captured (4th) launch onto k_dots
__global__ void k_nop() {}

// ---------------------------------------------------------------------------
// K3: dots key-part. CTA: 128 keys x 64 slots, 4 warps, warp tile 32x64.
// cp.async 3-stage pipeline, kc=16 (32 chunks). Key norms from smem (exact).
// ---------------------------------------------------------------------------
constexpr int SD_KINV = 0;                        // 128 floats
constexpr int SD_PIPE = 128;
constexpr int SD_ASZ  = 128 * 20;                 // 2560 floats per stage (A)
constexpr int SD_BSZ  = 64 * 20;                  // 1280 floats per stage (B)
constexpr int SD_STG  = SD_ASZ + SD_BSZ;          // 3840
constexpr int SD_CS   = SD_PIPE;                  // epilogue union (8448 <= 11520)
constexpr int SD_TOT  = SD_PIPE + 3 * SD_STG;     // 11648 floats = 46592 B

__global__ __launch_bounds__(128) void k_dots(const float* __restrict__ key,
                                              float* __restrict__ dout) {
    extern __shared__ float smf[];
    const uint32_t sb = smem_u32(smf);
    const int t = threadIdx.x, wid = t >> 5;
    const int b = blockIdx.y, n0blk = blockIdx.x * 128;
    const float* keyb = key + (long)b * N_ * D_;
    const int m0 = wid * 32;

    wmma::fragment<wmma::accumulator, 16, 16, 8, float> c[2][4];
#pragma unroll
    for (int i = 0; i < 2; i++)
#pragma unroll
        for (int j = 0; j < 4; j++) wmma::fill_fragment(c[i][j], 0.f);

    float ss = 0.f;

    auto issue = [&](int jc) {
        int s = jc % 3;
        uint32_t ab = sb + (SD_PIPE + s * SD_STG) * 4;
        uint32_t bb = ab + SD_ASZ * 4;
        const float* gA = keyb + (long)n0blk * D_ + jc * 16;
#pragma unroll
        for (int q = 0; q < 4; q++) {
            int idx = t + 128 * q, row = idx >> 2, f = idx & 3;
            cp16(ab + (row * 20 + f * 4) * 4, gA + (long)row * D_ + f * 4);
        }
#pragma unroll
        for (int q = 0; q < 2; q++) {
            int idx = t + 128 * q, row = idx >> 2, f = idx & 3;
            cp16(bb + (row * 20 + f * 4) * 4, g_shat + row * D_ + jc * 16 + f * 4);
        }
        cp_commit();
    };

    issue(0);
    issue(1);

    for (int jc = 0; jc < 32; jc++) {
        if (jc + 1 < 32) asm volatile("cp.async.wait_group 1;" ::: "memory");
        else             asm volatile("cp.async.wait_group 0;" ::: "memory");
        __syncthreads();
        if (jc + 2 < 32) issue(jc + 2);
        const int s = jc % 3;
        float* As = smf + SD_PIPE + s * SD_STG;
        float* Bs = As + SD_ASZ;
        // norm accumulation: thread t owns key row t (raw fp32, exact)
#pragma unroll
        for (int c0 = 0; c0 < 4; c0++) {
            int c2 = (c0 + (t >> 3)) & 3;
            float4 v = *(const float4*)(As + t * 20 + c2 * 4);
            ss += v.x * v.x + v.y * v.y + v.z * v.z + v.w * v.w;
        }
#pragma unroll
        for (int kk = 0; kk < 2; kk++) {
            int k0 = kk * 8;
            wmma::fragment<wmma::matrix_a, 16, 16, 8, wmma::precision::tf32, wmma::row_major> a0, a1;
            wmma::load_matrix_sync(a0, As + (m0)      * 20 + k0, 20);
            wmma::load_matrix_sync(a1, As + (m0 + 16) * 20 + k0, 20);
#pragma unroll
            for (int j = 0; j < 4; j++) {
                wmma::fragment<wmma::matrix_b, 16, 16, 8, wmma::precision::tf32, wmma::col_major> bf;
                wmma::load_matrix_sync(bf, Bs + (16 * j) * 20 + k0, 20);
                wmma::mma_sync(c[0][j], a0, bf, c[0][j]);
                wmma::mma_sync(c[1][j], a1, bf, c[1][j]);
            }
        }
    }

    smf[SD_KINV + t] = 1.f / fmaxf(sqrtf(ss), 1e-12f);
    __syncthreads();     // all consumption done; safe to overwrite pipeline with CS

    // C fragments -> smem col-major Cs[slot][key] (ld 132)
#pragma unroll
    for (int i = 0; i < 2; i++)
#pragma unroll
        for (int j = 0; j < 4; j++)
            wmma::store_matrix_sync(smf + SD_CS + (16 * j) * 132 + (m0 + 16 * i),
                                    c[i][j], 132, wmma::mem_col_major);
    __syncthreads();

    // write dots key-part: thread -> slot s = t>>1, key half kg = t&1
    {
        int s = t >> 1, kg = t & 1;
        const float* src = smf + SD_CS + s * 132 + kg * 64;
        const float* kv  = smf + SD_KINV + kg * 64;
        float* dst = dout + DOTS_OFF + (long)b * K_ * C_ + (long)s * C_ + K_ + n0blk + kg * 64;
#pragma unroll
        for (int g = 0; g < 16; g++) {
            float4 w = {src[g * 4 + 0] * kv[g * 4 + 0], src[g * 4 + 1] * kv[g * 4 + 1],
                        src[g * 4 + 2] * kv[g * 4 + 2], src[g * 4 + 3] * kv[g * 4 + 3]};
            *(float4*)(dst + g * 4) = w;
        }
    }
}

// ---------------------------------------------------------------------------
// K4: row softmax with block-causal mask -> g_attn (tf32-rounded);
// slot-slot dots -> output.
// ---------------------------------------------------------------------------
__global__ __launch_bounds__(256) void k_softmax(float* __restrict__ dout) {
    int row  = (blockIdx.x * blockDim.x + threadIdx.x) >> 5;
    int lane = threadIdx.x & 31;
    int b = row >> 6, i = row & 63;

    float* drow = dout + DOTS_OFF + (long)b * K_ * C_ + (long)i * C_;

    float sv[2], kvv[32];
    float m = -1e30f;
#pragma unroll
    for (int r = 0; r < 2; r++) {
        int c = lane + r * 32;
        float s = g_S[i * K_ + c];
        sv[r] = s;
        drow[c] = s;
        if (c < i) m = fmaxf(m, s);
    }
#pragma unroll
    for (int r = 0; r < 32; r++) {
        float v = drow[K_ + lane + r * 32];
        kvv[r] = v;
        m = fmaxf(m, v);
    }
#pragma unroll
    for (int o = 16; o; o >>= 1) m = fmaxf(m, __shfl_xor_sync(0xffffffffu, m, o));

    float sum = 0.f, es[2], ek[32];
#pragma unroll
    for (int r = 0; r < 2; r++) {
        int c = lane + r * 32;
        float x = (c < i) ? __expf((sv[r] - m) * TEMP_INV) : 0.f;
        es[r] = x; sum += x;
    }
#pragma unroll
    for (int r = 0; r < 32; r++) {
        float x = __expf((kvv[r] - m) * TEMP_INV);
        ek[r] = x; sum += x;
    }
#pragma unroll
    for (int o = 16; o; o >>= 1) sum += __shfl_xor_sync(0xffffffffu, sum, o);

    float inv = 1.f / (sum * (1.f + 1e-7f));
    float* at = g_attn + (long)row * C_;
#pragma unroll
    for (int r = 0; r < 2; r++) at[lane + r * 32] = to_tf32(es[r] * inv);
#pragma unroll
    for (int r = 0; r < 32; r++) at[K_ + lane + r * 32] = to_tf32(ek[r] * inv);
}

// ---------------------------------------------------------------------------
// K5: out = attn_n @ [slots; key_b]. CTA: 64 slots x 128 d, 4 warps,
// warp tile 32x64. cp.async 3-stage, kc=16 (68 chunks). Direct global store.
// ---------------------------------------------------------------------------
constexpr int SO_ASZ = 64 * 20;                   // 1280 floats per stage
constexpr int SO_BSZ = 16 * 132;                  // 2112
constexpr int SO_STG = SO_ASZ + SO_BSZ;           // 3392
constexpr int SO_TOT = 3 * SO_STG;                // 10176 floats = 40704 B

__global__ __launch_bounds__(128) void k_out(const float* __restrict__ slot,
                                             const float* __restrict__ key,
                                             float* __restrict__ dout) {
    extern __shared__ float smf[];
    const uint32_t sb = smem_u32(smf);
    const int t = threadIdx.x, wid = t >> 5;
    const int b = blockIdx.y, d0 = blockIdx.x * 128;
    const float* keyb  = key + (long)b * N_ * D_;
    const float* attnb = g_attn + (long)b * K_ * C_;

    const int m0 = (wid & 1) * 32;    // slot offset
    const int n0 = (wid >> 1) * 64;   // d offset

    wmma::fragment<wmma::accumulator, 16, 16, 8, float> c[2][4];
#pragma unroll
    for (int i = 0; i < 2; i++)
#pragma unroll
        for (int j = 0; j < 4; j++) wmma::fill_fragment(c[i][j], 0.f);

    auto issue = [&](int jc) {
        int s = jc % 3;
        uint32_t ab = sb + (s * SO_STG) * 4;
        uint32_t bb = ab + SO_ASZ * 4;
        // A: attn[64 x 16] = 256 float4, 2 per thread
#pragma unroll
        for (int q = 0; q < 2; q++) {
            int idx = t + 128 * q, row = idx >> 2, f = idx & 3;
            cp16(ab + (row * 20 + f * 4) * 4, attnb + (long)row * C_ + jc * 16 + f * 4);
        }
        // B: V[16 x 128] = 512 float4, 4 per thread (FIX: full coverage)
#pragma unroll
        for (int q = 0; q < 4; q++) {
            int idx = t + 128 * q, row = idx >> 5, f = idx & 31;
            int cc = jc * 16 + row;
            const float* src = (cc < K_) ? (slot + (long)cc * D_ + d0 + f * 4)
                                         : (keyb + (long)(cc - K_) * D_ + d0 + f * 4);
            cp16(bb + (row * 132 + f * 4) * 4, src);
        }
        cp_commit();
    };

    issue(0);
    issue(1);

    for (int jc = 0; jc < 68; jc++) {
        if (jc + 1 < 68) asm volatile("cp.async.wait_group 1;" ::: "memory");
        else             asm volatile("cp.async.wait_group 0;" ::: "memory");
        __syncthreads();
        if (jc + 2 < 68) issue(jc + 2);
        const int s = jc % 3;
        float* As = smf + s * SO_STG;
        float* Bs = As + SO_ASZ;
#pragma unroll
        for (int kk = 0; kk < 2; kk++) {
            int k0 = kk * 8;
            wmma::fragment<wmma::matrix_a, 16, 16, 8, wmma::precision::tf32, wmma::row_major> a0, a1;
            wmma::load_matrix_sync(a0, As + (m0)      * 20 + k0, 20);
            wmma::load_matrix_sync(a1, As + (m0 + 16) * 20 + k0, 20);
#pragma unroll
            for (int j = 0; j < 4; j++) {
                wmma::fragment<wmma::matrix_b, 16, 16, 8, wmma::precision::tf32, wmma::row_major> bf;
                wmma::load_matrix_sync(bf, Bs + k0 * 132 + n0 + 16 * j, 132);
                wmma::mma_sync(c[0][j], a0, bf, c[0][j]);
                wmma::mma_sync(c[1][j], a1, bf, c[1][j]);
            }
        }
    }

    // direct global store: out[b][slot][d]
#pragma unroll
    for (int i = 0; i < 2; i++)
#pragma unroll
        for (int j = 0; j < 4; j++) {
            float* gp = dout + (long)b * K_ * D_ + (long)(m0 + 16 * i) * D_ + d0 + n0 + 16 * j;
            wmma::store_matrix_sync(gp, c[i][j], D_, wmma::mem_row_major);
        }
}

// ---------------------------------------------------------------------------
extern "C" void kernel_launch(void* const* d_in, const int* in_sizes, int n_in,
                              void* d_out, int out_size) {
    const float* key  = (const float*)d_in[0];
    const float* slot = (const float*)d_in[1];
    float* out = (float*)d_out;

    cudaFuncSetAttribute(k_dots, cudaFuncAttributeMaxDynamicSharedMemorySize, SD_TOT * 4);
    cudaFuncSetAttribute(k_out,  cudaFuncAttributeMaxDynamicSharedMemorySize, SO_TOT * 4);

    k_slot_norm<<<K_, 128>>>(slot);
    k_slot_S<<<K_, K_>>>(slot);
    k_nop<<<1, 32>>>();                     // aligns ncu capture (4th launch) on k_dots
    k_dots<<<dim3(N_ / 128, B_), 128, SD_TOT * 4>>>(key, out);
    k_softmax<<<(B_ * K_) / 8, 256>>>(out);
    k_out<<<dim3(D_ / 128, B_), 128, SO_TOT * 4>>>(slot, key, out);
}